// round 15
// baseline (speedup 1.0000x reference)
#include <cuda_runtime.h>
#include <cuda_bf16.h>
#include <math.h>
#include <stdint.h>

#define N_TOK 4096
#define C 256
#define H 1024
#define E 32
#define ROUTED 31
#define MAXT 4096
#define PAIRS 16384
#define KC 32
#define ROWB 80
#define MATB (128 * ROWB)      // A hi or lo: 10240 B
#define ROWB2 272
#define MATB2 (KC * ROWB2)     // B hi or lo (128 n): 8704 B
#define BUFB (2 * MATB + 2 * MATB2)   // 37888 B
#define SMEM_TOT (2 * BUFB)           // 75776 B (opt-in)

__device__ int   g_counts[E];
__device__ int   g_tok[E * MAXT];
__device__ float g_gw [E * MAXT];
__device__ int   g_off[E];
__device__ float g_hid[(size_t)(PAIRS + 128) * H];
__device__ float g_scratch[4 * N_TOK * C];

__device__ __forceinline__ float gelu_tanh(float v) {
    float t = 0.7978845608028654f * (v + 0.044715f * v * v * v), th;
    asm("tanh.approx.f32 %0, %1;" : "=f"(th) : "f"(t));
    return 0.5f * v * (1.f + th);
}
__device__ __forceinline__ uint32_t hi2(float a, float b) {
    return __byte_perm(__float_as_uint(a), __float_as_uint(b), 0x7632);
}
__device__ __forceinline__ float trunchi(float a) {
    return __uint_as_float(__float_as_uint(a) & 0xFFFF0000u);
}
__device__ __forceinline__ void mma_bf16(float* d, const uint32_t* a, const uint32_t* b) {
    asm volatile("mma.sync.aligned.m16n8k16.row.col.f32.bf16.bf16.f32 "
        "{%0,%1,%2,%3},{%4,%5,%6,%7},{%8,%9},{%0,%1,%2,%3};"
        : "+f"(d[0]), "+f"(d[1]), "+f"(d[2]), "+f"(d[3])
        : "r"(a[0]), "r"(a[1]), "r"(a[2]), "r"(a[3]), "r"(b[0]), "r"(b[1]));
}
#define LDSM_X4(r, a) \
    asm volatile("ldmatrix.sync.aligned.m8n8.x4.shared.b16 {%0,%1,%2,%3}, [%4];" \
        : "=r"((r)[0]), "=r"((r)[1]), "=r"((r)[2]), "=r"((r)[3]) : "r"(a))
#define LDSM_X4T(r, a) \
    asm volatile("ldmatrix.sync.aligned.m8n8.x4.trans.shared.b16 {%0,%1,%2,%3}, [%4];" \
        : "=r"((r)[0]), "=r"((r)[1]), "=r"((r)[2]), "=r"((r)[3]) : "r"(a))

// buffer: [A_hi MATB][A_lo MATB][B_hi MATB2][B_lo MATB2]
// A: [128 m][ROWB] bf16 @ m*ROWB + k*2.  B: [KC k][ROWB2] bf16 @ k*ROWB2 + n*2 (128 n).
// 16 warps: wm = wid>>2, wn = wid&3; warp tile 32m x 32n.
// Three passes per kk so each accumulator's reuse distance is 8 independent MMAs.
__device__ __forceinline__ void mma_chunk(uint32_t smA, uint32_t smB, int lane,
                                          int wm, int wn, float (&d)[2][4][4])
{
    int row16 = lane & 15, half = (lane >> 4) & 1;
    #pragma unroll
    for (int kk = 0; kk < 2; kk++) {
        uint32_t ah[2][4], al[2][4], bh[4][2], bl[4][2];
        #pragma unroll
        for (int mi = 0; mi < 2; mi++) {
            uint32_t ad = smA + (wm * 32 + mi * 16 + row16) * ROWB + kk * 32 + half * 16;
            LDSM_X4(ah[mi], ad);
            LDSM_X4(al[mi], ad + MATB);
        }
        #pragma unroll
        for (int p = 0; p < 2; p++) {
            uint32_t bd = smB + (kk * 16 + row16) * ROWB2 + (wn * 32 + p * 16) * 2 + half * 16;
            uint32_t t[4];
            LDSM_X4T(t, bd);
            bh[2*p][0] = t[0]; bh[2*p][1] = t[1]; bh[2*p+1][0] = t[2]; bh[2*p+1][1] = t[3];
            LDSM_X4T(t, bd + MATB2);
            bl[2*p][0] = t[0]; bl[2*p][1] = t[1]; bl[2*p+1][0] = t[2]; bl[2*p+1][1] = t[3];
        }
        // pass 1: hi*hi (8 independent accumulators)
        #pragma unroll
        for (int mi = 0; mi < 2; mi++)
            #pragma unroll
            for (int nt = 0; nt < 4; nt++)
                mma_bf16(d[mi][nt], ah[mi], bh[nt]);
        // pass 2: hi*lo
        #pragma unroll
        for (int mi = 0; mi < 2; mi++)
            #pragma unroll
            for (int nt = 0; nt < 4; nt++)
                mma_bf16(d[mi][nt], ah[mi], bl[nt]);
        // pass 3: lo*hi
        #pragma unroll
        for (int mi = 0; mi < 2; mi++)
            #pragma unroll
            for (int nt = 0; nt < 4; nt++)
                mma_bf16(d[mi][nt], al[mi], bh[nt]);
    }
}

__device__ __forceinline__ void stageA(char* sm, int row, int seg, float4 v) {
    char* dp = sm + row * ROWB + seg * 8;
    float lx = v.x - trunchi(v.x), ly = v.y - trunchi(v.y);
    float lz = v.z - trunchi(v.z), lw = v.w - trunchi(v.w);
    *(uint2*)dp          = make_uint2(hi2(v.x, v.y), hi2(v.z, v.w));
    *(uint2*)(dp + MATB) = make_uint2(hi2(lx, ly), hi2(lz, lw));
}
__device__ __forceinline__ void stageB(char* sm, int row, int c4, float4 v) {
    char* dp = sm + 2 * MATB + row * ROWB2 + c4 * 8;
    float lx = v.x - trunchi(v.x), ly = v.y - trunchi(v.y);
    float lz = v.z - trunchi(v.z), lw = v.w - trunchi(v.w);
    *(uint2*)dp           = make_uint2(hi2(v.x, v.y), hi2(v.z, v.w));
    *(uint2*)(dp + MATB2) = make_uint2(hi2(lx, ly), hi2(lz, lw));
}

// ---------------- proven kernels ----------------
__global__ void zero_counts_kernel() { if (threadIdx.x < E) g_counts[threadIdx.x] = 0; }

__global__ void router_kernel(const float* __restrict__ x, const float* __restrict__ gW,
                              const float* __restrict__ gb, const float* __restrict__ ebias,
                              float* __restrict__ rw, int write_rw)
{
    const unsigned FULL = 0xffffffffu;
    int n = blockIdx.x, lane = threadIdx.x;
    __shared__ float xrow[C];
    for (int i = lane; i < C; i += 32) xrow[i] = x[n * C + i];
    __syncwarp();
    float logit = -1e30f;
    if (lane < ROUTED) {
        float acc = gb[lane];
        #pragma unroll 8
        for (int k = 0; k < C; k++) acc = fmaf(xrow[k], gW[k * ROUTED + lane], acc);
        logit = acc;
    }
    float m = logit;
    #pragma unroll
    for (int o = 16; o; o >>= 1) m = fmaxf(m, __shfl_xor_sync(FULL, m, o));
    float ev = (lane < ROUTED) ? expf(logit - m) : 0.f;
    float s = ev;
    #pragma unroll
    for (int o = 16; o; o >>= 1) s += __shfl_xor_sync(FULL, s, o);
    float biased = (lane < ROUTED) ? (ev / s + ebias[lane]) : -1e30f;
    float cur = biased;
    float tv0, tv1, tv2; int ti0, ti1, ti2;
    #pragma unroll
    for (int r = 0; r < 3; r++) {
        float bv = cur; int bi = lane;
        #pragma unroll
        for (int o = 16; o; o >>= 1) {
            float ov = __shfl_down_sync(FULL, bv, o);
            int   oi = __shfl_down_sync(FULL, bi, o);
            if (ov > bv || (ov == bv && oi < bi)) { bv = ov; bi = oi; }
        }
        bv = __shfl_sync(FULL, bv, 0); bi = __shfl_sync(FULL, bi, 0);
        if (r == 0) { tv0 = bv; ti0 = bi; } else if (r == 1) { tv1 = bv; ti1 = bi; }
        else { tv2 = bv; ti2 = bi; }
        if (lane == bi) cur = -1e30f;
    }
    float inv = 0.75f / (tv0 + tv1 + tv2);
    if (write_rw) {
        float v = 0.f;
        if (lane == 0)       v = 0.25f;
        if (lane == ti0 + 1) v = tv0 * inv;
        if (lane == ti1 + 1) v = tv1 * inv;
        if (lane == ti2 + 1) v = tv2 * inv;
        rw[n * E + lane] = v;
    }
    if (lane < 4) {
        int eidx; float g;
        if (lane == 0)      { eidx = 0;       g = 0.25f; }
        else if (lane == 1) { eidx = ti0 + 1; g = tv0 * inv; }
        else if (lane == 2) { eidx = ti1 + 1; g = tv1 * inv; }
        else                { eidx = ti2 + 1; g = tv2 * inv; }
        int pos = atomicAdd(&g_counts[eidx], 1);
        g_tok[eidx * MAXT + pos] = n | (lane << 16);
        g_gw [eidx * MAXT + pos] = g;
    }
}

__global__ void scan_kernel() {
    int off = 0;
    for (int e = 0; e < E; e++) { g_off[e] = off; off += g_counts[e]; }
}

__global__ void reduce_kernel(float* __restrict__ out)
{
    const int NC = N_TOK * C;
    int idx = blockIdx.x * blockDim.x + threadIdx.x;
    if (idx < NC)
        out[idx] = g_scratch[idx] + g_scratch[idx + NC]
                 + g_scratch[idx + 2 * NC] + g_scratch[idx + 3 * NC];
}

// ---------------- GEMM kernels: 128x128, 512 thr, double-buffered, MMA-first ----------------
extern __shared__ char dsm[];

__global__ __launch_bounds__(512, 1)
void gemm1_kernel(const float* __restrict__ x, const float* __restrict__ W1,
                  const float* __restrict__ b1)
{
    int e = blockIdx.z, tile = blockIdx.y, nch = blockIdx.x;   // nch in [0,8)
    int cnt = g_counts[e], base = tile * 128;
    if (base >= cnt) return;
    int nvalid = min(128, cnt - base);
    int tid = threadIdx.x, lane = tid & 31, wid = tid >> 5;
    int wm = wid >> 2, wn = wid & 3, g = lane >> 2, tg = lane & 3;
    uint32_t smBase = (uint32_t)__cvta_generic_to_shared(dsm);

    __shared__ int s_tok[128]; __shared__ float s_b[128];
    if (tid < 128) {
        s_tok[tid] = (tid < nvalid) ? (g_tok[e * MAXT + base + tid] & 0xFFFF) : 0;
        s_b[tid] = b1[e * H + nch * 128 + tid];
    }
    __syncthreads();

    float d[2][4][4];
    #pragma unroll
    for (int a = 0; a < 2; a++)
        #pragma unroll
        for (int b = 0; b < 4; b++)
            #pragma unroll
            for (int c = 0; c < 4; c++) d[a][b][c] = 0.f;

    const float* Bs = W1 + (size_t)e * C * H + nch * 128;   // [k][n] stride H
    const int NCH = C / KC;
    int arow = tid >> 3, aseg = tid & 7;
    int brow = tid >> 5, bseg = tid & 31;
    int arow2 = arow + 64, brow2 = brow + 16;

    float4 pa0, pa1, pb0, pb1;
    pa0 = *(const float4*)(x + (size_t)s_tok[arow] * C + aseg * 4);
    pa1 = *(const float4*)(x + (size_t)s_tok[arow2] * C + aseg * 4);
    pb0 = *(const float4*)(Bs + (size_t)brow * H + bseg * 4);
    pb1 = *(const float4*)(Bs + (size_t)brow2 * H + bseg * 4);
    stageA(dsm, arow, aseg, pa0); stageA(dsm, arow2, aseg, pa1);
    stageB(dsm, brow, bseg, pb0); stageB(dsm, brow2, bseg, pb1);
    pa0 = *(const float4*)(x + (size_t)s_tok[arow] * C + KC + aseg * 4);
    pa1 = *(const float4*)(x + (size_t)s_tok[arow2] * C + KC + aseg * 4);
    pb0 = *(const float4*)(Bs + (size_t)(KC + brow) * H + bseg * 4);
    pb1 = *(const float4*)(Bs + (size_t)(KC + brow2) * H + bseg * 4);
    __syncthreads();

    #pragma unroll 1
    for (int cs = 0; cs < NCH; cs++) {
        uint32_t smb = smBase + (cs & 1) * BUFB;
        mma_chunk(smb, smb + 2 * MATB, lane, wm, wn, d);
        if (cs + 1 < NCH) {
            char* nbuf = dsm + ((cs + 1) & 1) * BUFB;
            stageA(nbuf, arow, aseg, pa0); stageA(nbuf, arow2, aseg, pa1);
            stageB(nbuf, brow, bseg, pb0); stageB(nbuf, brow2, bseg, pb1);
        }
        if (cs + 2 < NCH) {
            int k0 = (cs + 2) * KC;
            pa0 = *(const float4*)(x + (size_t)s_tok[arow] * C + k0 + aseg * 4);
            pa1 = *(const float4*)(x + (size_t)s_tok[arow2] * C + k0 + aseg * 4);
            pb0 = *(const float4*)(Bs + (size_t)(k0 + brow) * H + bseg * 4);
            pb1 = *(const float4*)(Bs + (size_t)(k0 + brow2) * H + bseg * 4);
        }
        __syncthreads();
    }

    int p0 = g_off[e] + base;
    #pragma unroll
    for (int mi = 0; mi < 2; mi++)
        #pragma unroll
        for (int half = 0; half < 2; half++) {
            int m = wm * 32 + mi * 16 + g + half * 8;
            if (m < nvalid) {
                float* hrow = g_hid + (size_t)(p0 + m) * H + nch * 128;
                #pragma unroll
                for (int nt = 0; nt < 4; nt++) {
                    int col = wn * 32 + nt * 8 + tg * 2;
                    float2 o;
                    o.x = gelu_tanh(d[mi][nt][half * 2]     + s_b[col]);
                    o.y = gelu_tanh(d[mi][nt][half * 2 + 1] + s_b[col + 1]);
                    *(float2*)(hrow + col) = o;
                }
            }
        }
}

__global__ __launch_bounds__(512, 1)
void gemm2_kernel(const float* __restrict__ W2, const float* __restrict__ b2)
{
    int e = blockIdx.z, tile = blockIdx.y, cch = blockIdx.x;   // cch in [0,2)
    int cnt = g_counts[e], base = tile * 128;
    if (base >= cnt) return;
    int nvalid = min(128, cnt - base);
    int tid = threadIdx.x, lane = tid & 31, wid = tid >> 5;
    int wm = wid >> 2, wn = wid & 3, g = lane >> 2, tg = lane & 3;
    uint32_t smBase = (uint32_t)__cvta_generic_to_shared(dsm);
    int p0 = g_off[e] + base;

    __shared__ int s_ent[128]; __shared__ float s_gw[128]; __shared__ float s_b[128];
    if (tid < 128) {
        if (tid < nvalid) { s_ent[tid] = g_tok[e * MAXT + base + tid]; s_gw[tid] = g_gw[e * MAXT + base + tid]; }
        else              { s_ent[tid] = 0; s_gw[tid] = 0.f; }
        s_b[tid] = b2[e * C + cch * 128 + tid];
    }
    __syncthreads();

    float d[2][4][4];
    #pragma unroll
    for (int a = 0; a < 2; a++)
        #pragma unroll
        for (int b = 0; b < 4; b++)
            #pragma unroll
            for (int c = 0; c < 4; c++) d[a][b][c] = 0.f;

    const float* Bs = W2 + (size_t)e * H * C + cch * 128;   // [k][n] stride C
    const float* As = g_hid + (size_t)p0 * H;
    const int NCH = H / KC;
    int arow = tid >> 3, aseg = tid & 7;
    int brow = tid >> 5, bseg = tid & 31;
    int arow2 = arow + 64, brow2 = brow + 16;

    float4 pa0, pa1, pb0, pb1;
    pa0 = *(const float4*)(As + (size_t)arow * H + aseg * 4);
    pa1 = *(const float4*)(As + (size_t)arow2 * H + aseg * 4);
    pb0 = *(const float4*)(Bs + (size_t)brow * C + bseg * 4);
    pb1 = *(const float4*)(Bs + (size_t)brow2 * C + bseg * 4);
    stageA(dsm, arow, aseg, pa0); stageA(dsm, arow2, aseg, pa1);
    stageB(dsm, brow, bseg, pb0); stageB(dsm, brow2, bseg, pb1);
    pa0 = *(const float4*)(As + (size_t)arow * H + KC + aseg * 4);
    pa1 = *(const float4*)(As + (size_t)arow2 * H + KC + aseg * 4);
    pb0 = *(const float4*)(Bs + (size_t)(KC + brow) * C + bseg * 4);
    pb1 = *(const float4*)(Bs + (size_t)(KC + brow2) * C + bseg * 4);
    __syncthreads();

    #pragma unroll 1
    for (int cs = 0; cs < NCH; cs++) {
        uint32_t smb = smBase + (cs & 1) * BUFB;
        mma_chunk(smb, smb + 2 * MATB, lane, wm, wn, d);
        if (cs + 1 < NCH) {
            char* nbuf = dsm + ((cs + 1) & 1) * BUFB;
            stageA(nbuf, arow, aseg, pa0); stageA(nbuf, arow2, aseg, pa1);
            stageB(nbuf, brow, bseg, pb0); stageB(nbuf, brow2, bseg, pb1);
        }
        if (cs + 2 < NCH) {
            int k0 = (cs + 2) * KC;
            pa0 = *(const float4*)(As + (size_t)arow * H + k0 + aseg * 4);
            pa1 = *(const float4*)(As + (size_t)arow2 * H + k0 + aseg * 4);
            pb0 = *(const float4*)(Bs + (size_t)(k0 + brow) * C + bseg * 4);
            pb1 = *(const float4*)(Bs + (size_t)(k0 + brow2) * C + bseg * 4);
        }
        __syncthreads();
    }

    #pragma unroll
    for (int mi = 0; mi < 2; mi++)
        #pragma unroll
        for (int half = 0; half < 2; half++) {
            int m = wm * 32 + mi * 16 + g + half * 8;
            if (m < nvalid) {
                int ent = s_ent[m];
                int tok = ent & 0xFFFF, slot = ent >> 16;
                float gate = s_gw[m];
                float* dst = g_scratch + ((size_t)slot * N_TOK + tok) * C + cch * 128;
                #pragma unroll
                for (int nt = 0; nt < 4; nt++) {
                    int col = wn * 32 + nt * 8 + tg * 2;
                    float2 o;
                    o.x = (d[mi][nt][half * 2]     + s_b[col])     * gate;
                    o.y = (d[mi][nt][half * 2 + 1] + s_b[col + 1]) * gate;
                    *(float2*)(dst + col) = o;
                }
            }
        }
}

extern "C" void kernel_launch(void* const* d_in, const int* in_sizes, int n_in,
                              void* d_out, int out_size)
{
    const float* x  = (const float*)d_in[0];
    const float* gW = (const float*)d_in[1];
    const float* gb = (const float*)d_in[2];
    const float* eb = (const float*)d_in[3];
    const float* W1 = (const float*)d_in[4];
    const float* b1 = (const float*)d_in[5];
    const float* W2 = (const float*)d_in[6];
    const float* b2 = (const float*)d_in[7];
    float* out = (float*)d_out;

    int write_rw = (out_size >= N_TOK * C + N_TOK * E) ? 1 : 0;
    float* rw = out + N_TOK * C;

    cudaFuncSetAttribute(gemm1_kernel, cudaFuncAttributeMaxDynamicSharedMemorySize, SMEM_TOT);
    cudaFuncSetAttribute(gemm2_kernel, cudaFuncAttributeMaxDynamicSharedMemorySize, SMEM_TOT);

    zero_counts_kernel<<<1, 32>>>();
    router_kernel<<<N_TOK, 32>>>(x, gW, gb, eb, rw, write_rw);
    scan_kernel<<<1, 1>>>();
    gemm1_kernel<<<dim3(8, 32, E), 512, SMEM_TOT>>>(x, W1, b1);
    gemm2_kernel<<<dim3(2, 32, E), 512, SMEM_TOT>>>(W2, b2);
    reduce_kernel<<<(N_TOK * C + 255) / 256, 256>>>(out);
}

// round 16
// speedup vs baseline: 1.0401x; 1.0401x over previous
#include <cuda_runtime.h>
#include <cuda_bf16.h>
#include <math.h>
#include <stdint.h>

#define N_TOK 4096
#define C 256
#define H 1024
#define E 32
#define ROUTED 31
#define MAXT 4096
#define PAIRS 16384
#define KC 64
#define ROWB 144
#define MATB (128 * ROWB)      // A hi or lo: 18432 B
#define ROWB2 272
#define MATB2 (KC * ROWB2)     // B hi or lo: 17408 B
#define SMEM_TOT (2 * MATB + 2 * MATB2)   // 71680 B (opt-in)

__device__ int   g_counts[E];
__device__ int   g_tok[E * MAXT];
__device__ float g_gw [E * MAXT];
__device__ int   g_off[E];
__device__ float g_hid[(size_t)(PAIRS + 128) * H];
__device__ float g_scratch[4 * N_TOK * C];

__device__ __forceinline__ float gelu_tanh(float v) {
    float t = 0.7978845608028654f * (v + 0.044715f * v * v * v), th;
    asm("tanh.approx.f32 %0, %1;" : "=f"(th) : "f"(t));
    return 0.5f * v * (1.f + th);
}
__device__ __forceinline__ uint32_t hi2(float a, float b) {
    return __byte_perm(__float_as_uint(a), __float_as_uint(b), 0x7632);
}
__device__ __forceinline__ float trunchi(float a) {
    return __uint_as_float(__float_as_uint(a) & 0xFFFF0000u);
}
__device__ __forceinline__ void mma_bf16(float* d, const uint32_t* a, const uint32_t* b) {
    asm volatile("mma.sync.aligned.m16n8k16.row.col.f32.bf16.bf16.f32 "
        "{%0,%1,%2,%3},{%4,%5,%6,%7},{%8,%9},{%0,%1,%2,%3};"
        : "+f"(d[0]), "+f"(d[1]), "+f"(d[2]), "+f"(d[3])
        : "r"(a[0]), "r"(a[1]), "r"(a[2]), "r"(a[3]), "r"(b[0]), "r"(b[1]));
}
#define LDSM_X4(r, a) \
    asm volatile("ldmatrix.sync.aligned.m8n8.x4.shared.b16 {%0,%1,%2,%3}, [%4];" \
        : "=r"((r)[0]), "=r"((r)[1]), "=r"((r)[2]), "=r"((r)[3]) : "r"(a))
#define LDSM_X4T(r, a) \
    asm volatile("ldmatrix.sync.aligned.m8n8.x4.trans.shared.b16 {%0,%1,%2,%3}, [%4];" \
        : "=r"((r)[0]), "=r"((r)[1]), "=r"((r)[2]), "=r"((r)[3]) : "r"(a))

// smem: [A_hi MATB][A_lo MATB][B_hi MATB2][B_lo MATB2]
// A: [128 m][ROWB] bf16 @ m*ROWB + k*2 (64 k).  B: [KC k][ROWB2] bf16 @ k*ROWB2 + n*2 (128 n).
// 16 warps: wm = wid>>2, wn = wid&3; warp tile 32m x 32n; kk = 0..3.
__device__ __forceinline__ void mma_chunk(uint32_t smA, uint32_t smB, int lane,
                                          int wm, int wn, float (&d)[2][4][4])
{
    int row16 = lane & 15, half = (lane >> 4) & 1;
    #pragma unroll
    for (int kk = 0; kk < 4; kk++) {
        uint32_t ah[2][4], al[2][4], bh[4][2], bl[4][2];
        #pragma unroll
        for (int mi = 0; mi < 2; mi++) {
            uint32_t ad = smA + (wm * 32 + mi * 16 + row16) * ROWB + kk * 32 + half * 16;
            LDSM_X4(ah[mi], ad);
            LDSM_X4(al[mi], ad + MATB);
        }
        #pragma unroll
        for (int p = 0; p < 2; p++) {
            uint32_t bd = smB + (kk * 16 + row16) * ROWB2 + (wn * 32 + p * 16) * 2 + half * 16;
            uint32_t t[4];
            LDSM_X4T(t, bd);
            bh[2*p][0] = t[0]; bh[2*p][1] = t[1]; bh[2*p+1][0] = t[2]; bh[2*p+1][1] = t[3];
            LDSM_X4T(t, bd + MATB2);
            bl[2*p][0] = t[0]; bl[2*p][1] = t[1]; bl[2*p+1][0] = t[2]; bl[2*p+1][1] = t[3];
        }
        #pragma unroll
        for (int mi = 0; mi < 2; mi++)
            #pragma unroll
            for (int nt = 0; nt < 4; nt++) {
                mma_bf16(d[mi][nt], ah[mi], bh[nt]);
                mma_bf16(d[mi][nt], ah[mi], bl[nt]);
                mma_bf16(d[mi][nt], al[mi], bh[nt]);
            }
    }
}

// A: 128 rows x 64 k; slot s in [0,2048): row=s>>4, seg=s&15 (float4 units)
__device__ __forceinline__ void stageA(char* sm, int row, int seg, float4 v) {
    char* dp = sm + row * ROWB + seg * 8;
    float lx = v.x - trunchi(v.x), ly = v.y - trunchi(v.y);
    float lz = v.z - trunchi(v.z), lw = v.w - trunchi(v.w);
    *(uint2*)dp          = make_uint2(hi2(v.x, v.y), hi2(v.z, v.w));
    *(uint2*)(dp + MATB) = make_uint2(hi2(lx, ly), hi2(lz, lw));
}
// B: 64 k-rows x 128 n; slot s in [0,2048): row=s>>5, c4=s&31
__device__ __forceinline__ void stageB(char* sm, int row, int c4, float4 v) {
    char* dp = sm + 2 * MATB + row * ROWB2 + c4 * 8;
    float lx = v.x - trunchi(v.x), ly = v.y - trunchi(v.y);
    float lz = v.z - trunchi(v.z), lw = v.w - trunchi(v.w);
    *(uint2*)dp           = make_uint2(hi2(v.x, v.y), hi2(v.z, v.w));
    *(uint2*)(dp + MATB2) = make_uint2(hi2(lx, ly), hi2(lz, lw));
}

// ---------------- proven kernels ----------------
__global__ void zero_counts_kernel() { if (threadIdx.x < E) g_counts[threadIdx.x] = 0; }

__global__ void router_kernel(const float* __restrict__ x, const float* __restrict__ gW,
                              const float* __restrict__ gb, const float* __restrict__ ebias,
                              float* __restrict__ rw, int write_rw)
{
    const unsigned FULL = 0xffffffffu;
    int n = blockIdx.x, lane = threadIdx.x;
    __shared__ float xrow[C];
    for (int i = lane; i < C; i += 32) xrow[i] = x[n * C + i];
    __syncwarp();
    float logit = -1e30f;
    if (lane < ROUTED) {
        float acc = gb[lane];
        #pragma unroll 8
        for (int k = 0; k < C; k++) acc = fmaf(xrow[k], gW[k * ROUTED + lane], acc);
        logit = acc;
    }
    float m = logit;
    #pragma unroll
    for (int o = 16; o; o >>= 1) m = fmaxf(m, __shfl_xor_sync(FULL, m, o));
    float ev = (lane < ROUTED) ? expf(logit - m) : 0.f;
    float s = ev;
    #pragma unroll
    for (int o = 16; o; o >>= 1) s += __shfl_xor_sync(FULL, s, o);
    float biased = (lane < ROUTED) ? (ev / s + ebias[lane]) : -1e30f;
    float cur = biased;
    float tv0, tv1, tv2; int ti0, ti1, ti2;
    #pragma unroll
    for (int r = 0; r < 3; r++) {
        float bv = cur; int bi = lane;
        #pragma unroll
        for (int o = 16; o; o >>= 1) {
            float ov = __shfl_down_sync(FULL, bv, o);
            int   oi = __shfl_down_sync(FULL, bi, o);
            if (ov > bv || (ov == bv && oi < bi)) { bv = ov; bi = oi; }
        }
        bv = __shfl_sync(FULL, bv, 0); bi = __shfl_sync(FULL, bi, 0);
        if (r == 0) { tv0 = bv; ti0 = bi; } else if (r == 1) { tv1 = bv; ti1 = bi; }
        else { tv2 = bv; ti2 = bi; }
        if (lane == bi) cur = -1e30f;
    }
    float inv = 0.75f / (tv0 + tv1 + tv2);
    if (write_rw) {
        float v = 0.f;
        if (lane == 0)       v = 0.25f;
        if (lane == ti0 + 1) v = tv0 * inv;
        if (lane == ti1 + 1) v = tv1 * inv;
        if (lane == ti2 + 1) v = tv2 * inv;
        rw[n * E + lane] = v;
    }
    if (lane < 4) {
        int eidx; float g;
        if (lane == 0)      { eidx = 0;       g = 0.25f; }
        else if (lane == 1) { eidx = ti0 + 1; g = tv0 * inv; }
        else if (lane == 2) { eidx = ti1 + 1; g = tv1 * inv; }
        else                { eidx = ti2 + 1; g = tv2 * inv; }
        int pos = atomicAdd(&g_counts[eidx], 1);
        g_tok[eidx * MAXT + pos] = n | (lane << 16);
        g_gw [eidx * MAXT + pos] = g;
    }
}

__global__ void scan_kernel() {
    int off = 0;
    for (int e = 0; e < E; e++) { g_off[e] = off; off += g_counts[e]; }
}

__global__ void reduce_kernel(float* __restrict__ out)
{
    const int NC = N_TOK * C;
    int idx = blockIdx.x * blockDim.x + threadIdx.x;
    if (idx < NC)
        out[idx] = g_scratch[idx] + g_scratch[idx + NC]
                 + g_scratch[idx + 2 * NC] + g_scratch[idx + 3 * NC];
}

// ---------------- GEMM kernels: 128x128, 512 thr, KC=64, single buffer ----------------
extern __shared__ char dsm[];

__global__ __launch_bounds__(512, 1)
void gemm1_kernel(const float* __restrict__ x, const float* __restrict__ W1,
                  const float* __restrict__ b1)
{
    int e = blockIdx.z, tile = blockIdx.y, nch = blockIdx.x;   // nch in [0,8)
    int cnt = g_counts[e], base = tile * 128;
    if (base >= cnt) return;
    int nvalid = min(128, cnt - base);
    int tid = threadIdx.x, lane = tid & 31, wid = tid >> 5;
    int wm = wid >> 2, wn = wid & 3, g = lane >> 2, tg = lane & 3;
    uint32_t smA = (uint32_t)__cvta_generic_to_shared(dsm);
    uint32_t smB = smA + 2 * MATB;

    __shared__ int s_tok[128]; __shared__ float s_b[128];
    if (tid < 128) {
        s_tok[tid] = (tid < nvalid) ? (g_tok[e * MAXT + base + tid] & 0xFFFF) : 0;
        s_b[tid] = b1[e * H + nch * 128 + tid];
    }
    __syncthreads();

    float d[2][4][4];
    #pragma unroll
    for (int a = 0; a < 2; a++)
        #pragma unroll
        for (int b = 0; b < 4; b++)
            #pragma unroll
            for (int c = 0; c < 4; c++) d[a][b][c] = 0.f;

    const float* Bs = W1 + (size_t)e * C * H + nch * 128;   // [k][n] stride H
    const int NCH = C / KC;   // 4
    int arow = tid >> 2, aseg = (tid & 3);       // A: 4 slots/thread: s = tid + it*512
    int brow = tid >> 5, bseg = tid & 31;
    float4 pa[4], pb[4];
    #pragma unroll
    for (int it = 0; it < 4; it++) {
        int sA = tid + it * 512;
        int sB = tid + it * 512;
        pa[it] = *(const float4*)(x + (size_t)s_tok[sA >> 4] * C + (sA & 15) * 4);
        pb[it] = *(const float4*)(Bs + (size_t)(sB >> 5) * H + (sB & 31) * 4);
    }

    #pragma unroll 1
    for (int cs = 0; cs < NCH; cs++) {
        #pragma unroll
        for (int it = 0; it < 4; it++) {
            int sA = tid + it * 512;
            int sB = tid + it * 512;
            stageA(dsm, sA >> 4, sA & 15, pa[it]);
            stageB(dsm, sB >> 5, sB & 31, pb[it]);
        }
        if (cs + 1 < NCH) {
            int k0 = (cs + 1) * KC;
            #pragma unroll
            for (int it = 0; it < 4; it++) {
                int sA = tid + it * 512;
                int sB = tid + it * 512;
                pa[it] = *(const float4*)(x + (size_t)s_tok[sA >> 4] * C + k0 + (sA & 15) * 4);
                pb[it] = *(const float4*)(Bs + (size_t)(k0 + (sB >> 5)) * H + (sB & 31) * 4);
            }
        }
        __syncthreads();
        mma_chunk(smA, smB, lane, wm, wn, d);
        __syncthreads();
    }

    int p0 = g_off[e] + base;
    #pragma unroll
    for (int mi = 0; mi < 2; mi++)
        #pragma unroll
        for (int half = 0; half < 2; half++) {
            int m = wm * 32 + mi * 16 + g + half * 8;
            if (m < nvalid) {
                float* hrow = g_hid + (size_t)(p0 + m) * H + nch * 128;
                #pragma unroll
                for (int nt = 0; nt < 4; nt++) {
                    int col = wn * 32 + nt * 8 + tg * 2;
                    float2 o;
                    o.x = gelu_tanh(d[mi][nt][half * 2]     + s_b[col]);
                    o.y = gelu_tanh(d[mi][nt][half * 2 + 1] + s_b[col + 1]);
                    *(float2*)(hrow + col) = o;
                }
            }
        }
}

__global__ __launch_bounds__(512, 1)
void gemm2_kernel(const float* __restrict__ W2, const float* __restrict__ b2)
{
    int e = blockIdx.z, tile = blockIdx.y, cch = blockIdx.x;   // cch in [0,2)
    int cnt = g_counts[e], base = tile * 128;
    if (base >= cnt) return;
    int nvalid = min(128, cnt - base);
    int tid = threadIdx.x, lane = tid & 31, wid = tid >> 5;
    int wm = wid >> 2, wn = wid & 3, g = lane >> 2, tg = lane & 3;
    uint32_t smA = (uint32_t)__cvta_generic_to_shared(dsm);
    uint32_t smB = smA + 2 * MATB;
    int p0 = g_off[e] + base;

    __shared__ int s_ent[128]; __shared__ float s_gw[128]; __shared__ float s_b[128];
    if (tid < 128) {
        if (tid < nvalid) { s_ent[tid] = g_tok[e * MAXT + base + tid]; s_gw[tid] = g_gw[e * MAXT + base + tid]; }
        else              { s_ent[tid] = 0; s_gw[tid] = 0.f; }
        s_b[tid] = b2[e * C + cch * 128 + tid];
    }
    __syncthreads();

    float d[2][4][4];
    #pragma unroll
    for (int a = 0; a < 2; a++)
        #pragma unroll
        for (int b = 0; b < 4; b++)
            #pragma unroll
            for (int c = 0; c < 4; c++) d[a][b][c] = 0.f;

    const float* Bs = W2 + (size_t)e * H * C + cch * 128;   // [k][n] stride C
    const float* As = g_hid + (size_t)p0 * H;
    const int NCH = H / KC;   // 16
    float4 pa[4], pb[4];
    #pragma unroll
    for (int it = 0; it < 4; it++) {
        int sA = tid + it * 512;
        int sB = tid + it * 512;
        pa[it] = *(const float4*)(As + (size_t)(sA >> 4) * H + (sA & 15) * 4);
        pb[it] = *(const float4*)(Bs + (size_t)(sB >> 5) * C + (sB & 31) * 4);
    }

    #pragma unroll 1
    for (int cs = 0; cs < NCH; cs++) {
        #pragma unroll
        for (int it = 0; it < 4; it++) {
            int sA = tid + it * 512;
            int sB = tid + it * 512;
            stageA(dsm, sA >> 4, sA & 15, pa[it]);
            stageB(dsm, sB >> 5, sB & 31, pb[it]);
        }
        if (cs + 1 < NCH) {
            int k0 = (cs + 1) * KC;
            #pragma unroll
            for (int it = 0; it < 4; it++) {
                int sA = tid + it * 512;
                int sB = tid + it * 512;
                pa[it] = *(const float4*)(As + (size_t)(sA >> 4) * H + k0 + (sA & 15) * 4);
                pb[it] = *(const float4*)(Bs + (size_t)(k0 + (sB >> 5)) * C + (sB & 31) * 4);
            }
        }
        __syncthreads();
        mma_chunk(smA, smB, lane, wm, wn, d);
        __syncthreads();
    }

    #pragma unroll
    for (int mi = 0; mi < 2; mi++)
        #pragma unroll
        for (int half = 0; half < 2; half++) {
            int m = wm * 32 + mi * 16 + g + half * 8;
            if (m < nvalid) {
                int ent = s_ent[m];
                int tok = ent & 0xFFFF, slot = ent >> 16;
                float gate = s_gw[m];
                float* dst = g_scratch + ((size_t)slot * N_TOK + tok) * C + cch * 128;
                #pragma unroll
                for (int nt = 0; nt < 4; nt++) {
                    int col = wn * 32 + nt * 8 + tg * 2;
                    float2 o;
                    o.x = (d[mi][nt][half * 2]     + s_b[col])     * gate;
                    o.y = (d[mi][nt][half * 2 + 1] + s_b[col + 1]) * gate;
                    *(float2*)(dst + col) = o;
                }
            }
        }
}

extern "C" void kernel_launch(void* const* d_in, const int* in_sizes, int n_in,
                              void* d_out, int out_size)
{
    const float* x  = (const float*)d_in[0];
    const float* gW = (const float*)d_in[1];
    const float* gb = (const float*)d_in[2];
    const float* eb = (const float*)d_in[3];
    const float* W1 = (const float*)d_in[4];
    const float* b1 = (const float*)d_in[5];
    const float* W2 = (const float*)d_in[6];
    const float* b2 = (const float*)d_in[7];
    float* out = (float*)d_out;

    int write_rw = (out_size >= N_TOK * C + N_TOK * E) ? 1 : 0;
    float* rw = out + N_TOK * C;

    cudaFuncSetAttribute(gemm1_kernel, cudaFuncAttributeMaxDynamicSharedMemorySize, SMEM_TOT);
    cudaFuncSetAttribute(gemm2_kernel, cudaFuncAttributeMaxDynamicSharedMemorySize, SMEM_TOT);

    zero_counts_kernel<<<1, 32>>>();
    router_kernel<<<N_TOK, 32>>>(x, gW, gb, eb, rw, write_rw);
    scan_kernel<<<1, 1>>>();
    gemm1_kernel<<<dim3(8, 32, E), 512, SMEM_TOT>>>(x, W1, b1);
    gemm2_kernel<<<dim3(2, 32, E), 512, SMEM_TOT>>>(W2, b2);
    reduce_kernel<<<(N_TOK * C + 255) / 256, 256>>>(out);
}

// round 17
// speedup vs baseline: 1.0445x; 1.0043x over previous
#include <cuda_runtime.h>
#include <cuda_bf16.h>
#include <math.h>
#include <stdint.h>

#define N_TOK 4096
#define C 256
#define H 1024
#define E 32
#define ROUTED 31
#define MAXT 4096
#define PAIRS 16384
#define KC 32
#define ROWB 80
#define MATB (128 * ROWB)      // A hi or lo: 10240 B
#define ROWB2 272
#define MATB2 (KC * ROWB2)     // B hi or lo: 8704 B
#define SMEM_TOT (2 * MATB + 2 * MATB2)   // 37888 B < 48K

__device__ int   g_counts[E];
__device__ int   g_tok[E * MAXT];
__device__ float g_gw [E * MAXT];
__device__ int   g_off[E];
__device__ float g_hid[(size_t)(PAIRS + 128) * H];
__device__ float g_scratch[4 * N_TOK * C];

__device__ __forceinline__ float gelu_tanh(float v) {
    float t = 0.7978845608028654f * (v + 0.044715f * v * v * v), th;
    asm("tanh.approx.f32 %0, %1;" : "=f"(th) : "f"(t));
    return 0.5f * v * (1.f + th);
}
__device__ __forceinline__ uint32_t hi2(float a, float b) {
    return __byte_perm(__float_as_uint(a), __float_as_uint(b), 0x7632);
}
__device__ __forceinline__ float trunchi(float a) {
    return __uint_as_float(__float_as_uint(a) & 0xFFFF0000u);
}
__device__ __forceinline__ void mma_bf16(float* d, const uint32_t* a, const uint32_t* b) {
    asm volatile("mma.sync.aligned.m16n8k16.row.col.f32.bf16.bf16.f32 "
        "{%0,%1,%2,%3},{%4,%5,%6,%7},{%8,%9},{%0,%1,%2,%3};"
        : "+f"(d[0]), "+f"(d[1]), "+f"(d[2]), "+f"(d[3])
        : "r"(a[0]), "r"(a[1]), "r"(a[2]), "r"(a[3]), "r"(b[0]), "r"(b[1]));
}
#define LDSM_X4(r, a) \
    asm volatile("ldmatrix.sync.aligned.m8n8.x4.shared.b16 {%0,%1,%2,%3}, [%4];" \
        : "=r"((r)[0]), "=r"((r)[1]), "=r"((r)[2]), "=r"((r)[3]) : "r"(a))
#define LDSM_X4T(r, a) \
    asm volatile("ldmatrix.sync.aligned.m8n8.x4.trans.shared.b16 {%0,%1,%2,%3}, [%4];" \
        : "=r"((r)[0]), "=r"((r)[1]), "=r"((r)[2]), "=r"((r)[3]) : "r"(a))

// smem: [A_hi MATB][A_lo MATB][B_hi MATB2][B_lo MATB2]
// A: [128 m][ROWB] bf16 @ m*ROWB + k*2.  B: [KC k][ROWB2] bf16 @ k*ROWB2 + n*2 (128 n).
// 8 warps: wm = wid>>2 (0..1), wn = wid&3 (0..3); warp tile 64m x 32n (mi=4).
__device__ __forceinline__ void mma_chunk(uint32_t smA, uint32_t smB, int lane,
                                          int wm, int wn, float (&d)[4][4][4])
{
    int row16 = lane & 15, half = (lane >> 4) & 1;
    #pragma unroll
    for (int kk = 0; kk < 2; kk++) {
        uint32_t ah[4][4], al[4][4], bh[4][2], bl[4][2];
        #pragma unroll
        for (int mi = 0; mi < 4; mi++) {
            uint32_t ad = smA + (wm * 64 + mi * 16 + row16) * ROWB + kk * 32 + half * 16;
            LDSM_X4(ah[mi], ad);
            LDSM_X4(al[mi], ad + MATB);
        }
        #pragma unroll
        for (int p = 0; p < 2; p++) {
            uint32_t bd = smB + (kk * 16 + row16) * ROWB2 + (wn * 32 + p * 16) * 2 + half * 16;
            uint32_t t[4];
            LDSM_X4T(t, bd);
            bh[2*p][0] = t[0]; bh[2*p][1] = t[1]; bh[2*p+1][0] = t[2]; bh[2*p+1][1] = t[3];
            LDSM_X4T(t, bd + MATB2);
            bl[2*p][0] = t[0]; bl[2*p][1] = t[1]; bl[2*p+1][0] = t[2]; bl[2*p+1][1] = t[3];
        }
        #pragma unroll
        for (int mi = 0; mi < 4; mi++)
            #pragma unroll
            for (int nt = 0; nt < 4; nt++) {
                mma_bf16(d[mi][nt], ah[mi], bh[nt]);
                mma_bf16(d[mi][nt], ah[mi], bl[nt]);
                mma_bf16(d[mi][nt], al[mi], bh[nt]);
            }
    }
}

// A: 1024 float4 slots: row = s>>3, seg = s&7.  B: 1024 slots: row = s>>5, c4 = s&31.
__device__ __forceinline__ void stageA(char* sm, int row, int seg, float4 v) {
    char* dp = sm + row * ROWB + seg * 8;
    float lx = v.x - trunchi(v.x), ly = v.y - trunchi(v.y);
    float lz = v.z - trunchi(v.z), lw = v.w - trunchi(v.w);
    *(uint2*)dp          = make_uint2(hi2(v.x, v.y), hi2(v.z, v.w));
    *(uint2*)(dp + MATB) = make_uint2(hi2(lx, ly), hi2(lz, lw));
}
__device__ __forceinline__ void stageB(char* sm, int row, int c4, float4 v) {
    char* dp = sm + 2 * MATB + row * ROWB2 + c4 * 8;
    float lx = v.x - trunchi(v.x), ly = v.y - trunchi(v.y);
    float lz = v.z - trunchi(v.z), lw = v.w - trunchi(v.w);
    *(uint2*)dp           = make_uint2(hi2(v.x, v.y), hi2(v.z, v.w));
    *(uint2*)(dp + MATB2) = make_uint2(hi2(lx, ly), hi2(lz, lw));
}

// ---------------- proven kernels ----------------
__global__ void zero_counts_kernel() { if (threadIdx.x < E) g_counts[threadIdx.x] = 0; }

__global__ void router_kernel(const float* __restrict__ x, const float* __restrict__ gW,
                              const float* __restrict__ gb, const float* __restrict__ ebias,
                              float* __restrict__ rw, int write_rw)
{
    const unsigned FULL = 0xffffffffu;
    int n = blockIdx.x, lane = threadIdx.x;
    __shared__ float xrow[C];
    for (int i = lane; i < C; i += 32) xrow[i] = x[n * C + i];
    __syncwarp();
    float logit = -1e30f;
    if (lane < ROUTED) {
        float acc = gb[lane];
        #pragma unroll 8
        for (int k = 0; k < C; k++) acc = fmaf(xrow[k], gW[k * ROUTED + lane], acc);
        logit = acc;
    }
    float m = logit;
    #pragma unroll
    for (int o = 16; o; o >>= 1) m = fmaxf(m, __shfl_xor_sync(FULL, m, o));
    float ev = (lane < ROUTED) ? expf(logit - m) : 0.f;
    float s = ev;
    #pragma unroll
    for (int o = 16; o; o >>= 1) s += __shfl_xor_sync(FULL, s, o);
    float biased = (lane < ROUTED) ? (ev / s + ebias[lane]) : -1e30f;
    float cur = biased;
    float tv0, tv1, tv2; int ti0, ti1, ti2;
    #pragma unroll
    for (int r = 0; r < 3; r++) {
        float bv = cur; int bi = lane;
        #pragma unroll
        for (int o = 16; o; o >>= 1) {
            float ov = __shfl_down_sync(FULL, bv, o);
            int   oi = __shfl_down_sync(FULL, bi, o);
            if (ov > bv || (ov == bv && oi < bi)) { bv = ov; bi = oi; }
        }
        bv = __shfl_sync(FULL, bv, 0); bi = __shfl_sync(FULL, bi, 0);
        if (r == 0) { tv0 = bv; ti0 = bi; } else if (r == 1) { tv1 = bv; ti1 = bi; }
        else { tv2 = bv; ti2 = bi; }
        if (lane == bi) cur = -1e30f;
    }
    float inv = 0.75f / (tv0 + tv1 + tv2);
    if (write_rw) {
        float v = 0.f;
        if (lane == 0)       v = 0.25f;
        if (lane == ti0 + 1) v = tv0 * inv;
        if (lane == ti1 + 1) v = tv1 * inv;
        if (lane == ti2 + 1) v = tv2 * inv;
        rw[n * E + lane] = v;
    }
    if (lane < 4) {
        int eidx; float g;
        if (lane == 0)      { eidx = 0;       g = 0.25f; }
        else if (lane == 1) { eidx = ti0 + 1; g = tv0 * inv; }
        else if (lane == 2) { eidx = ti1 + 1; g = tv1 * inv; }
        else                { eidx = ti2 + 1; g = tv2 * inv; }
        int pos = atomicAdd(&g_counts[eidx], 1);
        g_tok[eidx * MAXT + pos] = n | (lane << 16);
        g_gw [eidx * MAXT + pos] = g;
    }
}

__global__ void scan_kernel() {
    int off = 0;
    for (int e = 0; e < E; e++) { g_off[e] = off; off += g_counts[e]; }
}

__global__ void reduce_kernel(float* __restrict__ out)
{
    const int NC = N_TOK * C;
    int idx = blockIdx.x * blockDim.x + threadIdx.x;
    if (idx < NC)
        out[idx] = g_scratch[idx] + g_scratch[idx + NC]
                 + g_scratch[idx + 2 * NC] + g_scratch[idx + 3 * NC];
}

// ---------------- GEMM kernels: 128x128, 256 thr, warp tile 64x32 ----------------
extern __shared__ char dsm[];

__global__ __launch_bounds__(256, 1)
void gemm1_kernel(const float* __restrict__ x, const float* __restrict__ W1,
                  const float* __restrict__ b1)
{
    int e = blockIdx.z, tile = blockIdx.y, nch = blockIdx.x;   // nch in [0,8)
    int cnt = g_counts[e], base = tile * 128;
    if (base >= cnt) return;
    int nvalid = min(128, cnt - base);
    int tid = threadIdx.x, lane = tid & 31, wid = tid >> 5;
    int wm = wid >> 2, wn = wid & 3, g = lane >> 2, tg = lane & 3;
    uint32_t smA = (uint32_t)__cvta_generic_to_shared(dsm);
    uint32_t smB = smA + 2 * MATB;

    __shared__ int s_tok[128]; __shared__ float s_b[128];
    if (tid < 128) {
        s_tok[tid] = (tid < nvalid) ? (g_tok[e * MAXT + base + tid] & 0xFFFF) : 0;
        s_b[tid] = b1[e * H + nch * 128 + tid];
    }
    __syncthreads();

    float d[4][4][4];
    #pragma unroll
    for (int a = 0; a < 4; a++)
        #pragma unroll
        for (int b = 0; b < 4; b++)
            #pragma unroll
            for (int c = 0; c < 4; c++) d[a][b][c] = 0.f;

    const float* Bs = W1 + (size_t)e * C * H + nch * 128;   // [k][n] stride H
    const int NCH = C / KC;   // 8
    float4 pa[4], pb[4];
    #pragma unroll
    for (int it = 0; it < 4; it++) {
        int s = tid + it * 256;
        pa[it] = *(const float4*)(x + (size_t)s_tok[s >> 3] * C + (s & 7) * 4);
        pb[it] = *(const float4*)(Bs + (size_t)(s >> 5) * H + (s & 31) * 4);
    }

    #pragma unroll 1
    for (int cs = 0; cs < NCH; cs++) {
        #pragma unroll
        for (int it = 0; it < 4; it++) {
            int s = tid + it * 256;
            stageA(dsm, s >> 3, s & 7, pa[it]);
            stageB(dsm, s >> 5, s & 31, pb[it]);
        }
        if (cs + 1 < NCH) {
            int k0 = (cs + 1) * KC;
            #pragma unroll
            for (int it = 0; it < 4; it++) {
                int s = tid + it * 256;
                pa[it] = *(const float4*)(x + (size_t)s_tok[s >> 3] * C + k0 + (s & 7) * 4);
                pb[it] = *(const float4*)(Bs + (size_t)(k0 + (s >> 5)) * H + (s & 31) * 4);
            }
        }
        __syncthreads();
        mma_chunk(smA, smB, lane, wm, wn, d);
        __syncthreads();
    }

    int p0 = g_off[e] + base;
    #pragma unroll
    for (int mi = 0; mi < 4; mi++)
        #pragma unroll
        for (int half = 0; half < 2; half++) {
            int m = wm * 64 + mi * 16 + g + half * 8;
            if (m < nvalid) {
                float* hrow = g_hid + (size_t)(p0 + m) * H + nch * 128;
                #pragma unroll
                for (int nt = 0; nt < 4; nt++) {
                    int col = wn * 32 + nt * 8 + tg * 2;
                    float2 o;
                    o.x = gelu_tanh(d[mi][nt][half * 2]     + s_b[col]);
                    o.y = gelu_tanh(d[mi][nt][half * 2 + 1] + s_b[col + 1]);
                    *(float2*)(hrow + col) = o;
                }
            }
        }
}

__global__ __launch_bounds__(256, 1)
void gemm2_kernel(const float* __restrict__ W2, const float* __restrict__ b2)
{
    int e = blockIdx.z, tile = blockIdx.y, cch = blockIdx.x;   // cch in [0,2)
    int cnt = g_counts[e], base = tile * 128;
    if (base >= cnt) return;
    int nvalid = min(128, cnt - base);
    int tid = threadIdx.x, lane = tid & 31, wid = tid >> 5;
    int wm = wid >> 2, wn = wid & 3, g = lane >> 2, tg = lane & 3;
    uint32_t smA = (uint32_t)__cvta_generic_to_shared(dsm);
    uint32_t smB = smA + 2 * MATB;
    int p0 = g_off[e] + base;

    __shared__ int s_ent[128]; __shared__ float s_gw[128]; __shared__ float s_b[128];
    if (tid < 128) {
        if (tid < nvalid) { s_ent[tid] = g_tok[e * MAXT + base + tid]; s_gw[tid] = g_gw[e * MAXT + base + tid]; }
        else              { s_ent[tid] = 0; s_gw[tid] = 0.f; }
        s_b[tid] = b2[e * C + cch * 128 + tid];
    }
    __syncthreads();

    float d[4][4][4];
    #pragma unroll
    for (int a = 0; a < 4; a++)
        #pragma unroll
        for (int b = 0; b < 4; b++)
            #pragma unroll
            for (int c = 0; c < 4; c++) d[a][b][c] = 0.f;

    const float* Bs = W2 + (size_t)e * H * C + cch * 128;   // [k][n] stride C
    const float* As = g_hid + (size_t)p0 * H;
    const int NCH = H / KC;   // 32
    float4 pa[4], pb[4];
    #pragma unroll
    for (int it = 0; it < 4; it++) {
        int s = tid + it * 256;
        pa[it] = *(const float4*)(As + (size_t)(s >> 3) * H + (s & 7) * 4);
        pb[it] = *(const float4*)(Bs + (size_t)(s >> 5) * C + (s & 31) * 4);
    }

    #pragma unroll 1
    for (int cs = 0; cs < NCH; cs++) {
        #pragma unroll
        for (int it = 0; it < 4; it++) {
            int s = tid + it * 256;
            stageA(dsm, s >> 3, s & 7, pa[it]);
            stageB(dsm, s >> 5, s & 31, pb[it]);
        }
        if (cs + 1 < NCH) {
            int k0 = (cs + 1) * KC;
            #pragma unroll
            for (int it = 0; it < 4; it++) {
                int s = tid + it * 256;
                pa[it] = *(const float4*)(As + (size_t)(s >> 3) * H + k0 + (s & 7) * 4);
                pb[it] = *(const float4*)(Bs + (size_t)(k0 + (s >> 5)) * C + (s & 31) * 4);
            }
        }
        __syncthreads();
        mma_chunk(smA, smB, lane, wm, wn, d);
        __syncthreads();
    }

    #pragma unroll
    for (int mi = 0; mi < 4; mi++)
        #pragma unroll
        for (int half = 0; half < 2; half++) {
            int m = wm * 64 + mi * 16 + g + half * 8;
            if (m < nvalid) {
                int ent = s_ent[m];
                int tok = ent & 0xFFFF, slot = ent >> 16;
                float gate = s_gw[m];
                float* dst = g_scratch + ((size_t)slot * N_TOK + tok) * C + cch * 128;
                #pragma unroll
                for (int nt = 0; nt < 4; nt++) {
                    int col = wn * 32 + nt * 8 + tg * 2;
                    float2 o;
                    o.x = (d[mi][nt][half * 2]     + s_b[col])     * gate;
                    o.y = (d[mi][nt][half * 2 + 1] + s_b[col + 1]) * gate;
                    *(float2*)(dst + col) = o;
                }
            }
        }
}

extern "C" void kernel_launch(void* const* d_in, const int* in_sizes, int n_in,
                              void* d_out, int out_size)
{
    const float* x  = (const float*)d_in[0];
    const float* gW = (const float*)d_in[1];
    const float* gb = (const float*)d_in[2];
    const float* eb = (const float*)d_in[3];
    const float* W1 = (const float*)d_in[4];
    const float* b1 = (const float*)d_in[5];
    const float* W2 = (const float*)d_in[6];
    const float* b2 = (const float*)d_in[7];
    float* out = (float*)d_out;

    int write_rw = (out_size >= N_TOK * C + N_TOK * E) ? 1 : 0;
    float* rw = out + N_TOK * C;

    zero_counts_kernel<<<1, 32>>>();
    router_kernel<<<N_TOK, 32>>>(x, gW, gb, eb, rw, write_rw);
    scan_kernel<<<1, 1>>>();
    gemm1_kernel<<<dim3(8, 32, E), 256, SMEM_TOT>>>(x, W1, b1);
    gemm2_kernel<<<dim3(2, 32, E), 256, SMEM_TOT>>>(W2, b2);
    reduce_kernel<<<(N_TOK * C + 255) / 256, 256>>>(out);
}